// round 1
// baseline (speedup 1.0000x reference)
#include <cuda_runtime.h>

// Problem constants
#define NN 32
#define CC 256
#define SS 30
#define HWD 256        // 16*16 pixels per frame
#define PP 16          // parts
#define CT 32          // channels per tile
#define PIXPAD 257     // padded pixel pitch (conflict-free both phases)

__device__ int g_lab64;

// Detect label dtype layout: int64 little-endian -> odd 32-bit words are all 0
// (labels are 0..15). int32 layout -> odd words are random labels, ~surely nonzero.
__global__ void detect_label_dtype(const int* __restrict__ lab)
{
    if (threadIdx.x == 0) {
        int any = 0;
        #pragma unroll 8
        for (int i = 1; i < 256; i += 2) any |= lab[i];
        g_lab64 = (any == 0) ? 1 : 0;
    }
}

__global__ __launch_bounds__(256, 6)
void part_pool_kernel(const float* __restrict__ x,
                      const void* __restrict__ labels_raw,
                      float* __restrict__ out)
{
    __shared__ float tile[CT * PIXPAD];   // 32,896 B
    __shared__ float pooled[CT * 17];     //  2,176 B
    __shared__ int   order[HWD];
    __shared__ int   cnt[PP];
    __shared__ int   off[PP];
    __shared__ int   fill[PP];

    const int f = blockIdx.x;             // frame = n*S + s, 0..959
    const int n = f / SS;
    const int s = f % SS;
    const int t = threadIdx.x;            // 0..255
    const int w = t >> 5;                 // warp 0..7
    const int l = t & 31;                 // lane = channel-in-tile

    // ---- per-frame label bucketing (once) ----
    if (t < PP) { cnt[t] = 0; fill[t] = 0; }
    __syncthreads();

    int myl;
    if (g_lab64) {
        const long long* lab = (const long long*)labels_raw;
        myl = (int)lab[f * HWD + t];
    } else {
        const int* lab = (const int*)labels_raw;
        myl = lab[f * HWD + t];
    }
    myl &= (PP - 1);                      // safety clamp
    atomicAdd(&cnt[myl], 1);
    __syncthreads();

    if (t == 0) {
        int acc = 0;
        #pragma unroll
        for (int p = 0; p < PP; p++) { off[p] = acc; acc += cnt[p]; }
    }
    __syncthreads();

    int pos = off[myl] + atomicAdd(&fill[myl], 1);
    order[pos] = t;
    __syncthreads();

    const float* xf = x + (size_t)n * CC * SS * HWD + (size_t)s * HWD;

    // ---- channel tiles ----
    for (int c0 = 0; c0 < CC; c0 += CT) {
        // load tile: CT*HWD scalar floats, fully coalesced gmem,
        // conflict-free smem stores (lanes vary pix)
        #pragma unroll
        for (int k = 0; k < (CT * HWD) / 256; k++) {
            int idx = t + k * 256;
            int pix = idx & (HWD - 1);
            int cl  = idx >> 8;
            tile[cl * PIXPAD + pix] = xf[(size_t)(c0 + cl) * (SS * HWD) + pix];
        }
        __syncthreads();

        // compute: warp w handles parts {w, w+8}; lane l = channel c0+l.
        // All lanes walk the same pixel list (order[] broadcast LDS);
        // tile reads conflict-free (lanes vary c, same pix).
        #pragma unroll
        for (int pi = 0; pi < 2; pi++) {
            int p  = w + pi * 8;
            int cN = cnt[p];
            int o  = off[p];
            float sum = 0.0f;
            float mx  = -3.0e38f;
            for (int j = 0; j < cN; j++) {
                int pix = order[o + j];
                float v = tile[l * PIXPAD + pix];
                sum += v;
                mx = fmaxf(mx, v);
            }
            float r = 0.0f;
            if (cN > 0)
                r = sum / (float)cN + fmaxf(mx, -100.0f);  // mean + (amax incl. -100 init)
            pooled[l * 17 + p] = r;
        }
        __syncthreads();

        // write out: 512 values, 64B-contiguous per (channel) chunk
        #pragma unroll
        for (int k = 0; k < (CT * PP) / 256; k++) {
            int idx = t + k * 256;
            int cl  = idx >> 4;
            int p   = idx & 15;
            out[((size_t)(n * CC + c0 + cl) * SS + s) * PP + p] = pooled[cl * 17 + p];
        }
        __syncthreads();
    }
}

extern "C" void kernel_launch(void* const* d_in, const int* in_sizes, int n_in,
                              void* d_out, int out_size)
{
    const float* x      = (const float*)d_in[0];
    const void*  labels = d_in[1];
    float*       out    = (float*)d_out;

    detect_label_dtype<<<1, 32>>>((const int*)labels);
    part_pool_kernel<<<NN * SS, 256>>>(x, labels, out);
}

// round 2
// speedup vs baseline: 1.0567x; 1.0567x over previous
#include <cuda_runtime.h>

#define NN 32
#define CC 256
#define SS 30
#define HWD 256        // 16*16 pixels per frame
#define PP 16          // parts
#define CT 32          // channels per tile
#define PIXPAD 257     // odd pitch -> conflict-free in both phases
#define TILES 4        // tiles per block (block covers 128 channels)

__device__ int g_lab64;

// Detect label dtype layout: int64 little-endian -> odd 32-bit words all 0.
__global__ void detect_label_dtype(const int* __restrict__ lab)
{
    if (threadIdx.x == 0) {
        int any = 0;
        #pragma unroll 8
        for (int i = 1; i < 256; i += 2) any |= lab[i];
        g_lab64 = (any == 0) ? 1 : 0;
    }
}

#define CP_ASYNC4(dst, src) \
    asm volatile("cp.async.ca.shared.global [%0], [%1], 4;" :: "r"(dst), "l"(src) : "memory")
#define CP_COMMIT() asm volatile("cp.async.commit_group;" ::: "memory")
#define CP_WAIT(n)  asm volatile("cp.async.wait_group %0;" :: "n"(n) : "memory")

__global__ __launch_bounds__(256, 3)
void part_pool_kernel(const float* __restrict__ x,
                      const void* __restrict__ labels_raw,
                      float* __restrict__ out)
{
    extern __shared__ float tiles[];      // 2 * CT*PIXPAD floats = 65,792 B
    __shared__ float pooled[CT * 17];
    __shared__ int   order[HWD];
    __shared__ int   cnt[PP];
    __shared__ int   off[PP];
    __shared__ int   fill[PP];

    const int bid  = blockIdx.x;          // 0..1919
    const int f    = bid >> 1;            // frame
    const int half = bid & 1;             // channel half (0: c 0-127, 1: c 128-255)
    const int n = f / SS;
    const int s = f % SS;
    const int t = threadIdx.x;
    const int w = t >> 5;
    const int l = t & 31;

    // ---- per-frame label bucketing ----
    if (t < PP) { cnt[t] = 0; fill[t] = 0; }
    __syncthreads();

    int myl;
    if (g_lab64) myl = (int)((const long long*)labels_raw)[(size_t)f * HWD + t];
    else         myl = ((const int*)labels_raw)[(size_t)f * HWD + t];
    myl &= (PP - 1);
    atomicAdd(&cnt[myl], 1);
    __syncthreads();

    if (t == 0) {
        int acc = 0;
        #pragma unroll
        for (int p = 0; p < PP; p++) { off[p] = acc; acc += cnt[p]; }
    }
    __syncthreads();
    order[off[myl] + atomicAdd(&fill[myl], 1)] = t;
    // order[] consumers pass a __syncthreads below before first compute.

    const float* xf = x + ((size_t)n * CC + half * (TILES * CT)) * (SS * HWD)
                        + (size_t)s * HWD;

    const unsigned stile = (unsigned)__cvta_generic_to_shared(tiles);

    // thread t copies pixel t of each of the tile's 32 channels (coalesced)
    #define LOAD_TILE(tt, buf) do {                                           \
        const float* _src = xf + (size_t)(tt) * CT * (SS * HWD) + t;          \
        unsigned _dst = stile + (unsigned)(((buf) * CT * PIXPAD + t) * 4);    \
        _Pragma("unroll")                                                     \
        for (int _k = 0; _k < CT; _k++)                                       \
            CP_ASYNC4(_dst + _k * (PIXPAD * 4), _src + (size_t)_k * (SS * HWD)); \
        CP_COMMIT();                                                          \
    } while (0)

    LOAD_TILE(0, 0);

    for (int tt = 0; tt < TILES; tt++) {
        const int buf = tt & 1;
        if (tt + 1 < TILES) { LOAD_TILE(tt + 1, buf ^ 1); CP_WAIT(1); }
        else                { CP_WAIT(0); }
        __syncthreads();                          // tile tt visible to all

        const float* tb = tiles + buf * (CT * PIXPAD);

        #pragma unroll
        for (int pi = 0; pi < 2; pi++) {
            const int p  = w + pi * 8;            // warp w owns parts {w, w+8}
            const int cN = cnt[p];
            const int o  = off[p];
            float sum = 0.0f;
            float mx  = -3.0e38f;
            for (int j = 0; j < cN; j++) {
                float v = tb[l * PIXPAD + order[o + j]];
                sum += v;
                mx = fmaxf(mx, v);
            }
            float r = 0.0f;
            if (cN > 0)
                r = sum / (float)cN + fmaxf(mx, -100.0f);
            pooled[l * 17 + p] = r;
        }
        __syncthreads();                          // pooled complete

        const int c0 = half * (TILES * CT) + tt * CT;
        #pragma unroll
        for (int k = 0; k < (CT * PP) / 256; k++) {
            int idx = t + k * 256;
            int cl  = idx >> 4;
            int p   = idx & 15;
            out[((size_t)(n * CC + c0 + cl) * SS + s) * PP + p] = pooled[cl * 17 + p];
        }
        // no trailing sync needed: next iter's CP_WAIT+__syncthreads orders
        // pooled/tile reuse, and next LOAD targets the buffer whose compute
        // finished before the sync above.
    }
    #undef LOAD_TILE
}

extern "C" void kernel_launch(void* const* d_in, const int* in_sizes, int n_in,
                              void* d_out, int out_size)
{
    const float* x      = (const float*)d_in[0];
    const void*  labels = d_in[1];
    float*       out    = (float*)d_out;

    cudaFuncSetAttribute(part_pool_kernel,
                         cudaFuncAttributeMaxDynamicSharedMemorySize,
                         2 * CT * PIXPAD * 4);

    detect_label_dtype<<<1, 32>>>((const int*)labels);
    part_pool_kernel<<<NN * SS * 2, 256, 2 * CT * PIXPAD * 4>>>(x, labels, out);
}

// round 3
// speedup vs baseline: 1.1117x; 1.0521x over previous
#include <cuda_runtime.h>

#define NN 32
#define CC 256
#define SS 30
#define HWD 256        // 16*16 pixels per frame
#define PP 16          // parts
#define CT 16          // channels per tile
#define PIT 257        // odd pitch -> conflict-free both phases
#define TILES 4        // tiles per block (block covers 64 channels)

__device__ int g_lab64;

// Detect label dtype layout: int64 little-endian -> odd 32-bit words all 0.
__global__ void detect_label_dtype(const int* __restrict__ lab)
{
    if (threadIdx.x == 0) {
        int any = 0;
        #pragma unroll 8
        for (int i = 1; i < 256; i += 2) any |= lab[i];
        g_lab64 = (any == 0) ? 1 : 0;
    }
}

#define CP_ASYNC4(dst, src) \
    asm volatile("cp.async.ca.shared.global [%0], [%1], 4;" :: "r"(dst), "l"(src) : "memory")
#define CP_COMMIT() asm volatile("cp.async.commit_group;" ::: "memory")
#define CP_WAIT(n)  asm volatile("cp.async.wait_group %0;" :: "n"(n) : "memory")

__global__ __launch_bounds__(256, 6)
void part_pool_kernel(const float* __restrict__ x,
                      const void* __restrict__ labels_raw,
                      float* __restrict__ out)
{
    extern __shared__ float tiles[];      // 2 * CT*PIT floats = 32,896 B
    __shared__ float pooled[CT * 17];
    __shared__ int   order[HWD];
    __shared__ int   cnt[PP];
    __shared__ int   off[PP];
    __shared__ int   fill[PP];

    const int bid = blockIdx.x;           // 0..3839
    const int f   = bid >> 2;             // frame
    const int q   = bid & 3;              // channel quarter (64 channels)
    const int n = f / SS;
    const int s = f % SS;
    const int t = threadIdx.x;
    const int w = t >> 5;
    const int l = t & 31;

    // ---- per-frame label bucketing ----
    if (t < PP) { cnt[t] = 0; fill[t] = 0; }
    __syncthreads();

    int myl;
    if (g_lab64) myl = (int)((const long long*)labels_raw)[(size_t)f * HWD + t];
    else         myl = ((const int*)labels_raw)[(size_t)f * HWD + t];
    myl &= (PP - 1);
    atomicAdd(&cnt[myl], 1);
    __syncthreads();

    if (t == 0) {
        int acc = 0;
        #pragma unroll
        for (int p = 0; p < PP; p++) { off[p] = acc; acc += cnt[p]; }
    }
    __syncthreads();
    order[off[myl] + atomicAdd(&fill[myl], 1)] = t;
    // order[] consumers pass a __syncthreads below before first compute.

    // base of this block's channel range for frame (n,s)
    const float* xf = x + ((size_t)(n * CC + q * (TILES * CT)) * SS + s) * HWD;

    const unsigned stile = (unsigned)__cvta_generic_to_shared(tiles);

    // tile = CT channels x 256 pixels; thread t copies 16 scalars, coalesced.
    #define LOAD_TILE(tt, buf) do {                                            \
        const float* _base = xf + (size_t)(tt) * CT * (SS * HWD);              \
        _Pragma("unroll")                                                      \
        for (int _k = 0; _k < (CT * HWD) / 256; _k++) {                        \
            int _idx = t + _k * 256;                                           \
            int _pix = _idx & (HWD - 1);                                       \
            int _cl  = _idx >> 8;                                              \
            unsigned _dst = stile + (unsigned)((((buf) * CT + _cl) * PIT + _pix) * 4); \
            CP_ASYNC4(_dst, _base + (size_t)_cl * (SS * HWD) + _pix);          \
        }                                                                      \
        CP_COMMIT();                                                           \
    } while (0)

    // per-lane fixed roles: half-warp owns one part, lane&15 = channel in tile
    const int p  = (w << 1) | (l >> 4);   // part 0..15
    const int cl = l & 15;                // channel-in-tile
    const int cN = cnt[p];
    const int o  = off[p];

    LOAD_TILE(0, 0);

    for (int tt = 0; tt < TILES; tt++) {
        const int buf = tt & 1;
        if (tt + 1 < TILES) { LOAD_TILE(tt + 1, buf ^ 1); CP_WAIT(1); }
        else                { CP_WAIT(0); }
        __syncthreads();                  // tile tt visible to all

        const float* tb = tiles + buf * (CT * PIT);

        float sum = 0.0f;
        float mx  = -3.0e38f;
        for (int j = 0; j < cN; j++) {
            float v = tb[cl * PIT + order[o + j]];
            sum += v;
            mx = fmaxf(mx, v);
        }
        float r = 0.0f;
        if (cN > 0)
            r = sum / (float)cN + fmaxf(mx, -100.0f);  // mean + amax(incl -100)
        pooled[cl * 17 + p] = r;

        __syncthreads();                  // pooled ready AND buffer reads done

        // coalesced store: thread t -> (channel t>>4, part t&15)
        {
            int cc = t >> 4;
            int pp = t & 15;
            int c  = q * (TILES * CT) + tt * CT + cc;
            out[((size_t)(n * CC + c) * SS + s) * PP + pp] = pooled[cc * 17 + pp];
        }
        // next iter's LOAD overwrites buf^1 (tile tt-1): its compute finished
        // before the sync above -> safe.
    }
    #undef LOAD_TILE
}

extern "C" void kernel_launch(void* const* d_in, const int* in_sizes, int n_in,
                              void* d_out, int out_size)
{
    const float* x      = (const float*)d_in[0];
    const void*  labels = d_in[1];
    float*       out    = (float*)d_out;

    cudaFuncSetAttribute(part_pool_kernel,
                         cudaFuncAttributeMaxDynamicSharedMemorySize,
                         2 * CT * PIT * 4);

    detect_label_dtype<<<1, 32>>>((const int*)labels);
    part_pool_kernel<<<NN * SS * 4, 256, 2 * CT * PIT * 4>>>(x, labels, out);
}

// round 4
// speedup vs baseline: 1.3937x; 1.2536x over previous
#include <cuda_runtime.h>

#define NN 32
#define CC 256
#define SS 30
#define HWD 256        // 16*16 pixels per frame
#define PP 16          // parts
#define CT 16          // channels per tile
#define PIT 260        // pitch: 16B-aligned rows, ≡4 (mod 8) -> 2-way worst-case LDS
#define TILES 4        // tiles per block (block covers 64 channels)

__device__ int g_lab64;

// Detect label dtype layout: int64 little-endian -> odd 32-bit words all 0.
__global__ void detect_label_dtype(const int* __restrict__ lab)
{
    if (threadIdx.x == 0) {
        int any = 0;
        #pragma unroll 8
        for (int i = 1; i < 256; i += 2) any |= lab[i];
        g_lab64 = (any == 0) ? 1 : 0;
    }
}

#define CP_ASYNC16(dst, src) \
    asm volatile("cp.async.cg.shared.global [%0], [%1], 16;" :: "r"(dst), "l"(src) : "memory")
#define CP_COMMIT() asm volatile("cp.async.commit_group;" ::: "memory")
#define CP_WAIT(n)  asm volatile("cp.async.wait_group %0;" :: "n"(n) : "memory")

__global__ __launch_bounds__(256, 6)
void part_pool_kernel(const float* __restrict__ x,
                      const void* __restrict__ labels_raw,
                      float* __restrict__ out)
{
    extern __shared__ float tiles[];      // 2 * CT*PIT floats = 33,280 B
    __shared__ float pooled[CT * 17];
    __shared__ int   order[HWD];
    __shared__ int   cnt[PP];
    __shared__ int   off[PP];
    __shared__ int   fill[PP];

    const int bid = blockIdx.x;           // 0..3839
    const int f   = bid >> 2;             // frame
    const int q   = bid & 3;              // channel quarter (64 channels)
    const int n = f / SS;
    const int s = f % SS;
    const int t = threadIdx.x;
    const int w = t >> 5;
    const int l = t & 31;

    // ---- per-frame label bucketing ----
    if (t < PP) { cnt[t] = 0; fill[t] = 0; }
    __syncthreads();

    int myl;
    if (g_lab64) myl = (int)((const long long*)labels_raw)[(size_t)f * HWD + t];
    else         myl = ((const int*)labels_raw)[(size_t)f * HWD + t];
    myl &= (PP - 1);
    atomicAdd(&cnt[myl], 1);
    __syncthreads();

    if (t == 0) {
        int acc = 0;
        #pragma unroll
        for (int p = 0; p < PP; p++) { off[p] = acc; acc += cnt[p]; }
    }
    __syncthreads();
    order[off[myl] + atomicAdd(&fill[myl], 1)] = t;
    // order[] consumers pass a __syncthreads below before first compute.

    // base of this block's channel range for frame (n,s)
    const float* xf = x + ((size_t)(n * CC + q * (TILES * CT)) * SS + s) * HWD;

    const unsigned stile = (unsigned)__cvta_generic_to_shared(tiles);

    // 16B cp.async: tile = 16 ch x 64 groups-of-4-pixels.
    // thread t: channel cl = t>>4, groups {(t&15) + 16k}. Fully coalesced
    // (lanes 0..15 cover a 256B contiguous span of one channel row).
    const int lcl = t >> 4;               // channel-in-tile for loads
    const int lg  = t & 15;               // base group for loads
    #define LOAD_TILE(tt, buf) do {                                            \
        const float* _row = xf + (size_t)((tt) * CT + lcl) * (SS * HWD);       \
        unsigned _dst = stile + (unsigned)(((buf) * CT + lcl) * (PIT * 4));    \
        _Pragma("unroll")                                                      \
        for (int _k = 0; _k < 4; _k++) {                                       \
            int _g = lg + 16 * _k;                                             \
            CP_ASYNC16(_dst + _g * 16, _row + _g * 4);                         \
        }                                                                      \
        CP_COMMIT();                                                           \
    } while (0)

    // per-lane fixed roles: half-warp owns one part, lane&15 = channel in tile
    const int p  = (w << 1) | (l >> 4);   // part 0..15
    const int cl = l & 15;                // channel-in-tile
    const int cN = cnt[p];
    const int o  = off[p];

    LOAD_TILE(0, 0);

    for (int tt = 0; tt < TILES; tt++) {
        const int buf = tt & 1;
        if (tt + 1 < TILES) { LOAD_TILE(tt + 1, buf ^ 1); CP_WAIT(1); }
        else                { CP_WAIT(0); }
        __syncthreads();                  // tile tt visible to all

        const float* tb = tiles + (buf * CT + cl) * PIT;

        float sum = 0.0f;
        float mx  = -3.0e38f;
        #pragma unroll 4
        for (int j = 0; j < cN; j++) {
            float v = tb[order[o + j]];   // order: broadcast LDS per half-warp
            sum += v;
            mx = fmaxf(mx, v);
        }
        float r = 0.0f;
        if (cN > 0)
            r = sum / (float)cN + fmaxf(mx, -100.0f);  // mean + amax(incl -100)
        pooled[cl * 17 + p] = r;

        __syncthreads();                  // pooled ready AND buffer reads done

        // coalesced store: thread t -> (channel t>>4, part t&15)
        {
            int cc = t >> 4;
            int pp = t & 15;
            int c  = q * (TILES * CT) + tt * CT + cc;
            out[((size_t)(n * CC + c) * SS + s) * PP + pp] = pooled[cc * 17 + pp];
        }
        // next iter's LOAD overwrites buf^1 (tile tt-1): its compute finished
        // before the sync above -> safe.
    }
    #undef LOAD_TILE
}

extern "C" void kernel_launch(void* const* d_in, const int* in_sizes, int n_in,
                              void* d_out, int out_size)
{
    const float* x      = (const float*)d_in[0];
    const void*  labels = d_in[1];
    float*       out    = (float*)d_out;

    cudaFuncSetAttribute(part_pool_kernel,
                         cudaFuncAttributeMaxDynamicSharedMemorySize,
                         2 * CT * PIT * 4);

    detect_label_dtype<<<1, 32>>>((const int*)labels);
    part_pool_kernel<<<NN * SS * 4, 256, 2 * CT * PIT * 4>>>(x, labels, out);
}